// round 1
// baseline (speedup 1.0000x reference)
#include <cuda_runtime.h>
#include <math.h>

#define NB 64
#define H  1024
#define LQ 1024

// ---- scratch (no allocations allowed) ----
__device__ float g_d[NB * H];       // b_dec + b_enc + dec_h @ W_dec
__device__ float g_scores[NB * LQ]; // pre-softmax scores
__device__ float g_ctx[NB * H];     // attention context

// ============================================================
// init: fold biases, zero ctx, seed h_att output with b_att
// ============================================================
__global__ void k_init(const float* __restrict__ b_dec,
                       const float* __restrict__ b_enc,
                       const float* __restrict__ b_att,
                       float* __restrict__ out_h) {
    int n = blockIdx.x;
    for (int j = threadIdx.x; j < H; j += blockDim.x) {
        g_d[n * H + j]   = b_dec[j] + b_enc[j];
        g_ctx[n * H + j] = 0.f;
        out_h[n * H + j] = b_att[j];
    }
}

// ============================================================
// C(64x1024) += A(64x1024) @ W(1024x1024)   (split-K atomics)
// A == nullptr -> use g_ctx as A.
// grid (16 n-tiles, 4 k-slices), 256 threads
// ============================================================
__global__ void k_gemm64(const float* __restrict__ A,
                         const float* __restrict__ W,
                         float* __restrict__ C) {
    __shared__ float As[64][17];
    __shared__ float Bs[16][64];
    const float* Ap = A ? A : g_ctx;
    int nt  = blockIdx.x;          // 0..15 : output column tile
    int ks  = blockIdx.y;          // 0..3  : K slice
    int tid = threadIdx.x;
    int tx = tid & 15, ty = tid >> 4;
    float acc[4][4] = {};
    int k0end = ks * 256 + 256;
    for (int k0 = ks * 256; k0 < k0end; k0 += 16) {
        int ka = tid & 15, ma = tid >> 4;
        #pragma unroll
        for (int i = 0; i < 4; i++)
            As[ma + 16 * i][ka] = Ap[(ma + 16 * i) * H + k0 + ka];
        int jb = tid & 63, kb = tid >> 6;
        #pragma unroll
        for (int q = 0; q < 4; q++)
            Bs[kb + 4 * q][jb] = W[(k0 + kb + 4 * q) * H + nt * 64 + jb];
        __syncthreads();
        #pragma unroll
        for (int kk = 0; kk < 16; kk++) {
            float a[4], b[4];
            #pragma unroll
            for (int i = 0; i < 4; i++) a[i] = As[ty * 4 + i][kk];
            #pragma unroll
            for (int j = 0; j < 4; j++) b[j] = Bs[kk][tx * 4 + j];
            #pragma unroll
            for (int i = 0; i < 4; i++)
                #pragma unroll
                for (int j = 0; j < 4; j++)
                    acc[i][j] += a[i] * b[j];
        }
        __syncthreads();
    }
    #pragma unroll
    for (int i = 0; i < 4; i++)
        #pragma unroll
        for (int j = 0; j < 4; j++)
            atomicAdd(&C[(ty * 4 + i) * H + nt * 64 + tx * 4 + j], acc[i][j]);
}

// ============================================================
// Fused: scores[n,l] = sum_d W_one[d] * tanh(g_d[n,d] + (enc[n,l,:] @ W_enc)[d])
// The e tensor is never materialized.
// grid (16 l-tiles, 64 n), 256 threads. Tile: 64 l-rows x 64 d-cols per pass.
// ============================================================
__global__ void k_score(const float* __restrict__ enc,
                        const float* __restrict__ Wenc,
                        const float* __restrict__ Wone) {
    __shared__ float As[64][17];
    __shared__ float Bs[16][64];
    __shared__ float ssc[64];
    int lt  = blockIdx.x;   // 0..15
    int n   = blockIdx.y;   // 0..63
    int tid = threadIdx.x;
    int tx = tid & 15, ty = tid >> 4;
    if (tid < 64) ssc[tid] = 0.f;
    const float* A    = enc + ((long)n * LQ + lt * 64) * H;
    const float* dvec = g_d + n * H;
    __syncthreads();

    for (int dc0 = 0; dc0 < H; dc0 += 64) {
        float acc[4][4] = {};
        for (int k0 = 0; k0 < H; k0 += 16) {
            int ka = tid & 15, ma = tid >> 4;
            #pragma unroll
            for (int i = 0; i < 4; i++)
                As[ma + 16 * i][ka] = A[(ma + 16 * i) * H + k0 + ka];
            int jb = tid & 63, kb = tid >> 6;
            #pragma unroll
            for (int q = 0; q < 4; q++)
                Bs[kb + 4 * q][jb] = Wenc[(k0 + kb + 4 * q) * H + dc0 + jb];
            __syncthreads();
            #pragma unroll
            for (int kk = 0; kk < 16; kk++) {
                float a[4], b[4];
                #pragma unroll
                for (int i = 0; i < 4; i++) a[i] = As[ty * 4 + i][kk];
                #pragma unroll
                for (int j = 0; j < 4; j++) b[j] = Bs[kk][tx * 4 + j];
                #pragma unroll
                for (int i = 0; i < 4; i++)
                    #pragma unroll
                    for (int j = 0; j < 4; j++)
                        acc[i][j] += a[i] * b[j];
            }
            __syncthreads();
        }
        // epilogue: partial score dot for this 64-col chunk
        #pragma unroll
        for (int i = 0; i < 4; i++) {
            float p = 0.f;
            #pragma unroll
            for (int j = 0; j < 4; j++) {
                int dc = dc0 + tx * 4 + j;
                p += Wone[dc] * tanhf(dvec[dc] + acc[i][j]);
            }
            // reduce across the 16 tx threads owning this row (within half-warp)
            #pragma unroll
            for (int o = 8; o > 0; o >>= 1)
                p += __shfl_xor_sync(0xffffffffu, p, o);
            if (tx == 0) ssc[ty * 4 + i] += p;   // single writer per row
        }
        __syncthreads();
    }
    if (tid < 64) g_scores[n * LQ + lt * 64 + tid] = ssc[tid];
}

// ============================================================
// softmax over L=1024 per batch row; writes alpha to output
// ============================================================
__global__ void k_softmax(float* __restrict__ alpha_out) {
    __shared__ float rbuf[8];
    int n = blockIdx.x, tid = threadIdx.x;  // 256 threads
    const float* s = g_scores + n * LQ;
    float v[4], mx = -1e30f;
    #pragma unroll
    for (int i = 0; i < 4; i++) { v[i] = s[tid + 256 * i]; mx = fmaxf(mx, v[i]); }
    #pragma unroll
    for (int o = 16; o > 0; o >>= 1) mx = fmaxf(mx, __shfl_xor_sync(0xffffffffu, mx, o));
    if ((tid & 31) == 0) rbuf[tid >> 5] = mx;
    __syncthreads();
    mx = rbuf[0];
    #pragma unroll
    for (int w = 1; w < 8; w++) mx = fmaxf(mx, rbuf[w]);
    __syncthreads();
    float e[4], sum = 0.f;
    #pragma unroll
    for (int i = 0; i < 4; i++) { e[i] = expf(v[i] - mx); sum += e[i]; }
    #pragma unroll
    for (int o = 16; o > 0; o >>= 1) sum += __shfl_xor_sync(0xffffffffu, sum, o);
    if ((tid & 31) == 0) rbuf[tid >> 5] = sum;
    __syncthreads();
    float tot = 0.f;
    #pragma unroll
    for (int w = 0; w < 8; w++) tot += rbuf[w];
    float inv = 1.f / tot;
    #pragma unroll
    for (int i = 0; i < 4; i++) alpha_out[n * LQ + tid + 256 * i] = e[i] * inv;
}

// ============================================================
// ctx[n,:] += sum_l alpha[n,l] * enc[n,l,:]  (streaming, float4)
// grid (16 l-slices, 64 n), 256 threads
// ============================================================
__global__ void k_ctx(const float* __restrict__ enc,
                      const float* __restrict__ alpha) {
    int ls = blockIdx.x, n = blockIdx.y, tid = threadIdx.x;
    const float*  al   = alpha + n * LQ + ls * 64;
    const float4* base = (const float4*)(enc + ((long)n * LQ + ls * 64) * H) + tid;
    float4 acc = {0.f, 0.f, 0.f, 0.f};
    #pragma unroll 4
    for (int l = 0; l < 64; l++) {
        float  a = al[l];
        float4 v = base[l * (H / 4)];
        acc.x += a * v.x; acc.y += a * v.y; acc.z += a * v.z; acc.w += a * v.w;
    }
    float* c = g_ctx + n * H + tid * 4;
    atomicAdd(c + 0, acc.x);
    atomicAdd(c + 1, acc.y);
    atomicAdd(c + 2, acc.z);
    atomicAdd(c + 3, acc.w);
}

// ============================================================
extern "C" void kernel_launch(void* const* d_in, const int* in_sizes, int n_in,
                              void* d_out, int out_size) {
    const float* dec_h = (const float*)d_in[0];
    const float* enc   = (const float*)d_in[1];
    const float* W_dec = (const float*)d_in[2];
    const float* b_dec = (const float*)d_in[3];
    const float* W_enc = (const float*)d_in[4];
    const float* b_enc = (const float*)d_in[5];
    const float* W_one = (const float*)d_in[6];
    // d_in[7] = b_one: cancels in softmax, unused
    const float* W_att = (const float*)d_in[8];
    const float* b_att = (const float*)d_in[9];

    float* out_h = (float*)d_out;            // h_att_curr: 64x1024
    float* alpha = (float*)d_out + NB * H;   // alpha:      64x1024

    k_init<<<NB, 256>>>(b_dec, b_enc, b_att, out_h);

    // g_d += dec_h @ W_dec  (C = g_d via the pattern: pass g_d through... use a
    // dedicated launch with C pointing at scratch via a trampoline kernel arg)
    // We cannot take &g_d on host; k_gemm64 with A given writes to C param, so
    // route both scratch cases through device symbols: A=nullptr -> g_ctx.
    // For C=g_d we launch a variant below.
    {
        // dec projection: C must be g_d -> use k_gemm64_dst_gd
        extern __global__ void k_gemm64_to_gd(const float*, const float*);
        k_gemm64_to_gd<<<dim3(16, 4), 256>>>(dec_h, W_dec);
    }

    k_score<<<dim3(16, NB), 256>>>(enc, W_enc, W_one);
    k_softmax<<<NB, 256>>>(alpha);
    k_ctx<<<dim3(16, NB), 256>>>(enc, alpha);
    k_gemm64<<<dim3(16, 4), 256>>>(nullptr /*g_ctx*/, W_att, out_h);
}

// variant writing into device-symbol g_d (host cannot pass its address cheaply)
__global__ void k_gemm64_to_gd(const float* __restrict__ A,
                               const float* __restrict__ W) {
    __shared__ float As[64][17];
    __shared__ float Bs[16][64];
    int nt  = blockIdx.x;
    int ks  = blockIdx.y;
    int tid = threadIdx.x;
    int tx = tid & 15, ty = tid >> 4;
    float acc[4][4] = {};
    int k0end = ks * 256 + 256;
    for (int k0 = ks * 256; k0 < k0end; k0 += 16) {
        int ka = tid & 15, ma = tid >> 4;
        #pragma unroll
        for (int i = 0; i < 4; i++)
            As[ma + 16 * i][ka] = A[(ma + 16 * i) * H + k0 + ka];
        int jb = tid & 63, kb = tid >> 6;
        #pragma unroll
        for (int q = 0; q < 4; q++)
            Bs[kb + 4 * q][jb] = W[(k0 + kb + 4 * q) * H + nt * 64 + jb];
        __syncthreads();
        #pragma unroll
        for (int kk = 0; kk < 16; kk++) {
            float a[4], b[4];
            #pragma unroll
            for (int i = 0; i < 4; i++) a[i] = As[ty * 4 + i][kk];
            #pragma unroll
            for (int j = 0; j < 4; j++) b[j] = Bs[kk][tx * 4 + j];
            #pragma unroll
            for (int i = 0; i < 4; i++)
                #pragma unroll
                for (int j = 0; j < 4; j++)
                    acc[i][j] += a[i] * b[j];
        }
        __syncthreads();
    }
    #pragma unroll
    for (int i = 0; i < 4; i++)
        #pragma unroll
        for (int j = 0; j < 4; j++)
            atomicAdd(&g_d[(ty * 4 + i) * H + nt * 64 + tx * 4 + j], acc[i][j]);
}